// round 1
// baseline (speedup 1.0000x reference)
#include <cuda_runtime.h>

#define NPOS 32768
#define NB 2
#define DIM 256
#define HID 512
#define QKV_M 1536
#define SCALE 0.125f

// Scratch (device globals: allocation-free per harness rules)
__device__ float g_qkv[(size_t)NB * QKV_M * NPOS];   // [b][o][n], o: q=0..511, k=512..1023, v=1024..1535
__device__ float g_att[(size_t)NB * HID * NPOS];     // [b][c][n]

typedef unsigned long long ull;

__device__ __forceinline__ void fma2(ull& c, ull a, ull b) {
    asm("fma.rn.f32x2 %0, %1, %2, %0;" : "+l"(c) : "l"(a), "l"(b));
}
__device__ __forceinline__ ull splat2(float a) {
    ull r; asm("mov.b64 %0, {%1, %1};" : "=l"(r) : "f"(a)); return r;
}
__device__ __forceinline__ float2 unpack2(ull v) {
    float2 f; asm("mov.b64 {%0, %1}, %2;" : "=f"(f.x), "=f"(f.y) : "l"(v)); return f;
}

// ---------------------------------------------------------------------------
// Generic 128x128 SGEMM: C[m][n] = sum_k A[m][k] * B[k][n] (+bias[m])
// A: [M x K] row-major (weights, shared across batch)
// B: [K x NPOS] row-major, batch stride sB ; C: [M x NPOS], batch stride sC
// 256 threads, BK=16, 8x8 micro-tile with packed f32x2 FMA.
// ---------------------------------------------------------------------------
__global__ __launch_bounds__(256) void sgemm128(
    const float* __restrict__ A, const float* __restrict__ B,
    float* __restrict__ C, const float* __restrict__ bias,
    int M, int K, long long sB, long long sC)
{
    __shared__ float As[16][128];   // transposed A tile: As[k][m]
    __shared__ float Bs[16][128];   // Bs[k][n]

    const float* Bp = B + (size_t)blockIdx.z * sB;
    float* Cp = C + (size_t)blockIdx.z * sC;
    const int m0 = blockIdx.y * 128;
    const int n0 = blockIdx.x * 128;
    const int tid = threadIdx.x;
    const int tx = tid & 15;        // n direction
    const int ty = tid >> 4;        // m direction
    const int ar = tid >> 2, ac = (tid & 3) << 2;
    const int br = tid >> 5, bc = (tid & 31) << 2;

    ull acc[8][4];
#pragma unroll
    for (int i = 0; i < 8; i++)
#pragma unroll
        for (int j = 0; j < 4; j++) acc[i][j] = 0ULL;

    for (int k0 = 0; k0 < K; k0 += 16) {
#pragma unroll
        for (int rr = 0; rr < 2; rr++) {
            int r = ar + rr * 64;
            float4 av = *(const float4*)&A[(size_t)(m0 + r) * K + k0 + ac];
            As[ac + 0][r] = av.x; As[ac + 1][r] = av.y;
            As[ac + 2][r] = av.z; As[ac + 3][r] = av.w;
        }
#pragma unroll
        for (int rr = 0; rr < 2; rr++) {
            int r = br + rr * 8;
            *(float4*)&Bs[r][bc] = *(const float4*)&Bp[(size_t)(k0 + r) * NPOS + n0 + bc];
        }
        __syncthreads();
#pragma unroll
        for (int kk = 0; kk < 16; kk++) {
            float4 a0 = *(const float4*)&As[kk][ty * 8];
            float4 a1 = *(const float4*)&As[kk][ty * 8 + 4];
            ulonglong2 b01 = *(const ulonglong2*)&Bs[kk][tx * 8];
            ulonglong2 b23 = *(const ulonglong2*)&Bs[kk][tx * 8 + 4];
            ull av[8] = {splat2(a0.x), splat2(a0.y), splat2(a0.z), splat2(a0.w),
                         splat2(a1.x), splat2(a1.y), splat2(a1.z), splat2(a1.w)};
            ull bv[4] = {b01.x, b01.y, b23.x, b23.y};
#pragma unroll
            for (int i = 0; i < 8; i++)
#pragma unroll
                for (int j = 0; j < 4; j++)
                    fma2(acc[i][j], av[i], bv[j]);
        }
        __syncthreads();
    }

#pragma unroll
    for (int i = 0; i < 8; i++) {
        int m = m0 + ty * 8 + i;
        float bb = (bias != nullptr) ? __ldg(&bias[m]) : 0.0f;
        float2 p0 = unpack2(acc[i][0]), p1 = unpack2(acc[i][1]);
        float2 p2 = unpack2(acc[i][2]), p3 = unpack2(acc[i][3]);
        float4 v0 = make_float4(p0.x + bb, p0.y + bb, p1.x + bb, p1.y + bb);
        float4 v1 = make_float4(p2.x + bb, p2.y + bb, p3.x + bb, p3.y + bb);
        *(float4*)&Cp[(size_t)m * NPOS + n0 + tx * 8] = v0;
        *(float4*)&Cp[(size_t)m * NPOS + n0 + tx * 8 + 4] = v1;
    }
}

// ---------------------------------------------------------------------------
// Windowed attention: one block = (b, h, window, i-tile of 64 queries).
// S = (Q^T K) * SCALE  -> swizzled P^T[j][i] in smem (fp32, 128 KB)
// softmax (unnormalized exp; 1/rowsum folded into O epilogue)
// O[i][d] = sum_j P[i][j] V[d][j], written channel-major to g_att.
// ---------------------------------------------------------------------------
#define QS 68
#define KS 132
#define VS 129

// swizzled float index of P^T[j][i]  (i handled in aligned groups of 4)
__device__ __forceinline__ int ppos(int j, int i) {
    return j * 64 + ((((i >> 2) ^ ((j >> 3) & 15)) << 2) | (i & 3));
}

__global__ __launch_bounds__(256) void attn_win()
{
    extern __shared__ float smf[];
    float* sQ  = smf;                      // [64][68]
    float* sKV = smf + 64 * QS;            // K: [64][132] / V: [64][129]
    float* sPT = sKV + 64 * KS;            // [512][64] swizzled
    float* red = sPT + 512 * 64;           // [4][64]
    float* inv = red + 256;                // [64]

    const int tid = threadIdx.x;
    const int bx = blockIdx.x;
    const int it = bx & 7;
    const int widx = bx >> 3;
    const int b  = widx >> 9;
    const int h  = (widx >> 6) & 7;
    const int wd = widx & 63;

    const size_t qoff = ((size_t)(b * QKV_M) + h * 64) * NPOS + wd * 512 + it * 64;
    const size_t koff = ((size_t)(b * QKV_M) + 512 + h * 64) * NPOS + wd * 512;
    const size_t voff = koff + (size_t)512 * NPOS;
    const size_t ooff = ((size_t)(b * HID) + h * 64) * NPOS + wd * 512 + it * 64;

    // ---- load Q tile [64 d][64 i] ----
    {
        int i4 = (tid & 15) * 4;
        int d0 = tid >> 4;
#pragma unroll
        for (int p = 0; p < 4; p++) {
            int d = d0 + p * 16;
            *(float4*)&sQ[d * QS + i4] = *(const float4*)&g_qkv[qoff + (size_t)d * NPOS + i4];
        }
    }

    const int tx = tid & 15, ty = tid >> 4;

    // ---- S = Q^T K (4 chunks of 128 j) ----
    for (int jc = 0; jc < 4; jc++) {
        {
            int j4 = (tid & 31) * 4;
            int d0 = tid >> 5;
#pragma unroll
            for (int p = 0; p < 8; p++) {
                int d = d0 + p * 8;
                *(float4*)&sKV[d * KS + j4] =
                    *(const float4*)&g_qkv[koff + (size_t)d * NPOS + jc * 128 + j4];
            }
        }
        __syncthreads();

        ull acc[4][4];
#pragma unroll
        for (int i = 0; i < 4; i++)
#pragma unroll
            for (int j = 0; j < 4; j++) acc[i][j] = 0ULL;

#pragma unroll 8
        for (int d = 0; d < 64; d++) {
            float4 a = *(const float4*)&sQ[d * QS + ty * 4];
            ulonglong2 b01 = *(const ulonglong2*)&sKV[d * KS + tx * 8];
            ulonglong2 b23 = *(const ulonglong2*)&sKV[d * KS + tx * 8 + 4];
            ull av[4] = {splat2(a.x), splat2(a.y), splat2(a.z), splat2(a.w)};
            ull bv[4] = {b01.x, b01.y, b23.x, b23.y};
#pragma unroll
            for (int i = 0; i < 4; i++)
#pragma unroll
                for (int j = 0; j < 4; j++)
                    fma2(acc[i][j], av[i], bv[j]);
        }
        // store scaled S^T into swizzled sPT
#pragma unroll
        for (int j2 = 0; j2 < 4; j2++) {
            float2 r0 = unpack2(acc[0][j2]);
            float2 r1 = unpack2(acc[1][j2]);
            float2 r2 = unpack2(acc[2][j2]);
            float2 r3 = unpack2(acc[3][j2]);
            int j = jc * 128 + tx * 8 + j2 * 2;
            float4 v0 = make_float4(r0.x * SCALE, r1.x * SCALE, r2.x * SCALE, r3.x * SCALE);
            *(float4*)&sPT[ppos(j, ty * 4)] = v0;
            int j1 = j + 1;
            float4 v1 = make_float4(r0.y * SCALE, r1.y * SCALE, r2.y * SCALE, r3.y * SCALE);
            *(float4*)&sPT[ppos(j1, ty * 4)] = v1;
        }
        __syncthreads();
    }

    // ---- softmax (store exp; keep 1/rowsum for epilogue) ----
    {
        int i = tid & 63;
        int jg = tid >> 6;
        float mx = -1e30f;
        for (int s = 0; s < 128; s++) {
            int j = jg * 128 + s;
            mx = fmaxf(mx, sPT[ppos(j, i)]);
        }
        red[jg * 64 + i] = mx;
        __syncthreads();
        if (tid < 64)
            inv[tid] = fmaxf(fmaxf(red[tid], red[64 + tid]), fmaxf(red[128 + tid], red[192 + tid]));
        __syncthreads();
        float rmax = inv[i];
        float sum = 0.0f;
        for (int s = 0; s < 128; s++) {
            int j = jg * 128 + s;
            int idx = ppos(j, i);
            float e = __expf(sPT[idx] - rmax);
            sPT[idx] = e;
            sum += e;
        }
        red[jg * 64 + i] = sum;
        __syncthreads();
        if (tid < 64)
            inv[tid] = 1.0f / (red[tid] + red[64 + tid] + red[128 + tid] + red[192 + tid]);
        __syncthreads();
    }

    // ---- O = P V (reduction over j, 4 chunks of 128) ----
    ull oa[2][4];
#pragma unroll
    for (int i = 0; i < 2; i++)
#pragma unroll
        for (int j = 0; j < 4; j++) oa[i][j] = 0ULL;

    for (int jc = 0; jc < 4; jc++) {
        {
            int j4 = (tid & 31) * 4;
            int d0 = tid >> 5;
#pragma unroll
            for (int p = 0; p < 8; p++) {
                int d = d0 + p * 8;
                float4 v = *(const float4*)&g_qkv[voff + (size_t)d * NPOS + jc * 128 + j4];
                sKV[d * VS + j4 + 0] = v.x;
                sKV[d * VS + j4 + 1] = v.y;
                sKV[d * VS + j4 + 2] = v.z;
                sKV[d * VS + j4 + 3] = v.w;
            }
        }
        __syncthreads();
#pragma unroll 4
        for (int s = 0; s < 128; s++) {
            int j = jc * 128 + s;
            ulonglong2 ap = *(const ulonglong2*)&sPT[ppos(j, ty * 4)];
#pragma unroll
            for (int dd = 0; dd < 4; dd++) {
                ull bs = splat2(sKV[(tx * 4 + dd) * VS + s]);
                fma2(oa[0][dd], ap.x, bs);
                fma2(oa[1][dd], ap.y, bs);
            }
        }
        __syncthreads();
    }

    // ---- epilogue: normalize rows, write channel-major O ----
    float iv0 = inv[ty * 4 + 0], iv1 = inv[ty * 4 + 1];
    float iv2 = inv[ty * 4 + 2], iv3 = inv[ty * 4 + 3];
#pragma unroll
    for (int dd = 0; dd < 4; dd++) {
        float2 p0 = unpack2(oa[0][dd]);
        float2 p1 = unpack2(oa[1][dd]);
        float4 v = make_float4(p0.x * iv0, p0.y * iv1, p1.x * iv2, p1.y * iv3);
        *(float4*)&g_att[ooff + (size_t)(tx * 4 + dd) * NPOS + ty * 4] = v;
    }
}

// ---------------------------------------------------------------------------
extern "C" void kernel_launch(void* const* d_in, const int* in_sizes, int n_in,
                              void* d_out, int out_size)
{
    const float* x     = (const float*)d_in[0];
    const float* w_qkv = (const float*)d_in[1];
    const float* w_out = (const float*)d_in[2];
    const float* b_out = (const float*)d_in[3];
    float* out = (float*)d_out;

    float* qkv; cudaGetSymbolAddress((void**)&qkv, g_qkv);
    float* att; cudaGetSymbolAddress((void**)&att, g_att);

    const int smem_attn = (64 * QS + 64 * KS + 512 * 64 + 256 + 64) * 4;
    cudaFuncSetAttribute(attn_win, cudaFuncAttributeMaxDynamicSharedMemorySize, smem_attn);

    // QKV projection: [1536,256] x [256,32768] per batch
    dim3 gA(NPOS / 128, QKV_M / 128, NB);
    sgemm128<<<gA, 256>>>(w_qkv, x, qkv, nullptr, QKV_M, DIM,
                          (long long)DIM * NPOS, (long long)QKV_M * NPOS);

    // Windowed attention: 2 b * 8 h * 64 windows * 8 i-tiles = 8192 blocks
    attn_win<<<8192, 256, smem_attn>>>();

    // Output projection + bias: [256,512] x [512,32768] per batch
    dim3 gC(NPOS / 128, DIM / 128, NB);
    sgemm128<<<gC, 256>>>(w_out, att, out, b_out, DIM, HID,
                          (long long)HID * NPOS, (long long)DIM * NPOS);
}

// round 2
// speedup vs baseline: 1.5971x; 1.5971x over previous
#include <cuda_runtime.h>

#define NPOS 32768
#define NB 2
#define DIM 256
#define HID 512
#define QKV_M 1536
#define SCALE 0.125f

// Scratch (device globals: allocation-free per harness rules)
__device__ float g_qkv[(size_t)NB * QKV_M * NPOS];   // [b][o][n], o: q=0..511, k=512..1023, v=1024..1535
__device__ float g_att[(size_t)NB * HID * NPOS];     // [b][c][n]

typedef unsigned long long ull;

__device__ __forceinline__ void fma2(ull& c, ull a, ull b) {
    asm("fma.rn.f32x2 %0, %1, %2, %0;" : "+l"(c) : "l"(a), "l"(b));
}
__device__ __forceinline__ ull splat2(float a) {
    ull r; asm("mov.b64 %0, {%1, %1};" : "=l"(r) : "f"(a)); return r;
}
__device__ __forceinline__ float2 unpack2(ull v) {
    float2 f; asm("mov.b64 {%0, %1}, %2;" : "=f"(f.x), "=f"(f.y) : "l"(v)); return f;
}

// ---------------------------------------------------------------------------
// Generic 128x128 SGEMM: C[m][n] = sum_k A[m][k] * B[k][n] (+bias[m])
// A: [M x K] row-major (weights, shared across batch)
// B: [K x NPOS] row-major, batch stride sB ; C: [M x NPOS], batch stride sC
// 256 threads, BK=16, 8x8 micro-tile with packed f32x2 FMA.
// ---------------------------------------------------------------------------
__global__ __launch_bounds__(256) void sgemm128(
    const float* __restrict__ A, const float* __restrict__ B,
    float* __restrict__ C, const float* __restrict__ bias,
    int M, int K, long long sB, long long sC)
{
    __shared__ float As[16][128];   // transposed A tile: As[k][m]
    __shared__ float Bs[16][128];   // Bs[k][n]

    const float* Bp = B + (size_t)blockIdx.z * sB;
    float* Cp = C + (size_t)blockIdx.z * sC;
    const int m0 = blockIdx.y * 128;
    const int n0 = blockIdx.x * 128;
    const int tid = threadIdx.x;
    const int tx = tid & 15;        // n direction
    const int ty = tid >> 4;        // m direction
    const int ar = tid >> 2, ac = (tid & 3) << 2;
    const int br = tid >> 5, bc = (tid & 31) << 2;

    ull acc[8][4];
#pragma unroll
    for (int i = 0; i < 8; i++)
#pragma unroll
        for (int j = 0; j < 4; j++) acc[i][j] = 0ULL;

    for (int k0 = 0; k0 < K; k0 += 16) {
#pragma unroll
        for (int rr = 0; rr < 2; rr++) {
            int r = ar + rr * 64;
            float4 av = *(const float4*)&A[(size_t)(m0 + r) * K + k0 + ac];
            As[ac + 0][r] = av.x; As[ac + 1][r] = av.y;
            As[ac + 2][r] = av.z; As[ac + 3][r] = av.w;
        }
#pragma unroll
        for (int rr = 0; rr < 2; rr++) {
            int r = br + rr * 8;
            *(float4*)&Bs[r][bc] = *(const float4*)&Bp[(size_t)(k0 + r) * NPOS + n0 + bc];
        }
        __syncthreads();
#pragma unroll
        for (int kk = 0; kk < 16; kk++) {
            float4 a0 = *(const float4*)&As[kk][ty * 8];
            float4 a1 = *(const float4*)&As[kk][ty * 8 + 4];
            ulonglong2 b01 = *(const ulonglong2*)&Bs[kk][tx * 8];
            ulonglong2 b23 = *(const ulonglong2*)&Bs[kk][tx * 8 + 4];
            ull av[8] = {splat2(a0.x), splat2(a0.y), splat2(a0.z), splat2(a0.w),
                         splat2(a1.x), splat2(a1.y), splat2(a1.z), splat2(a1.w)};
            ull bv[4] = {b01.x, b01.y, b23.x, b23.y};
#pragma unroll
            for (int i = 0; i < 8; i++)
#pragma unroll
                for (int j = 0; j < 4; j++)
                    fma2(acc[i][j], av[i], bv[j]);
        }
        __syncthreads();
    }

#pragma unroll
    for (int i = 0; i < 8; i++) {
        int m = m0 + ty * 8 + i;
        float bb = (bias != nullptr) ? __ldg(&bias[m]) : 0.0f;
        float2 p0 = unpack2(acc[i][0]), p1 = unpack2(acc[i][1]);
        float2 p2 = unpack2(acc[i][2]), p3 = unpack2(acc[i][3]);
        float4 v0 = make_float4(p0.x + bb, p0.y + bb, p1.x + bb, p1.y + bb);
        float4 v1 = make_float4(p2.x + bb, p2.y + bb, p3.x + bb, p3.y + bb);
        *(float4*)&Cp[(size_t)m * NPOS + n0 + tx * 8] = v0;
        *(float4*)&Cp[(size_t)m * NPOS + n0 + tx * 8 + 4] = v1;
    }
}

// ---------------------------------------------------------------------------
// Windowed attention: one block = (b, h, window, i-tile of 64 queries).
// S = (Q^T K) * SCALE  -> swizzled P^T[j][i] in smem (fp32, 128 KB)
// softmax (unnormalized exp; 1/rowsum folded into O epilogue)
// O[i][d] = sum_j P[i][j] V[d][j], written channel-major to g_att.
// ---------------------------------------------------------------------------
#define QS 68
#define KS 132
#define VS 129

// swizzled float index of P^T[j][i]  (i handled in aligned groups of 4)
__device__ __forceinline__ int ppos(int j, int i) {
    return j * 64 + ((((i >> 2) ^ ((j >> 3) & 15)) << 2) | (i & 3));
}

__global__ __launch_bounds__(256) void attn_win()
{
    extern __shared__ float smf[];
    float* sQ  = smf;                      // [64][68]
    float* sKV = smf + 64 * QS;            // K: [64][132] / V: [64][129]
    float* sPT = sKV + 64 * KS;            // [512][64] swizzled
    float* red = sPT + 512 * 64;           // [4][64]
    float* inv = red + 256;                // [64]

    const int tid = threadIdx.x;
    const int bx = blockIdx.x;
    const int it = bx & 7;
    const int widx = bx >> 3;
    const int b  = widx >> 9;
    const int h  = (widx >> 6) & 7;
    const int wd = widx & 63;

    const size_t qoff = ((size_t)(b * QKV_M) + h * 64) * NPOS + wd * 512 + it * 64;
    const size_t koff = ((size_t)(b * QKV_M) + 512 + h * 64) * NPOS + wd * 512;
    const size_t voff = koff + (size_t)512 * NPOS;
    const size_t ooff = ((size_t)(b * HID) + h * 64) * NPOS + wd * 512 + it * 64;

    // ---- load Q tile [64 d][64 i] ----
    {
        int i4 = (tid & 15) * 4;
        int d0 = tid >> 4;
#pragma unroll
        for (int p = 0; p < 4; p++) {
            int d = d0 + p * 16;
            *(float4*)&sQ[d * QS + i4] = *(const float4*)&g_qkv[qoff + (size_t)d * NPOS + i4];
        }
    }

    const int tx = tid & 15, ty = tid >> 4;

    // ---- S = Q^T K (4 chunks of 128 j) ----
    for (int jc = 0; jc < 4; jc++) {
        {
            int j4 = (tid & 31) * 4;
            int d0 = tid >> 5;
#pragma unroll
            for (int p = 0; p < 8; p++) {
                int d = d0 + p * 8;
                *(float4*)&sKV[d * KS + j4] =
                    *(const float4*)&g_qkv[koff + (size_t)d * NPOS + jc * 128 + j4];
            }
        }
        __syncthreads();

        ull acc[4][4];
#pragma unroll
        for (int i = 0; i < 4; i++)
#pragma unroll
            for (int j = 0; j < 4; j++) acc[i][j] = 0ULL;

#pragma unroll 8
        for (int d = 0; d < 64; d++) {
            float4 a = *(const float4*)&sQ[d * QS + ty * 4];
            ulonglong2 b01 = *(const ulonglong2*)&sKV[d * KS + tx * 8];
            ulonglong2 b23 = *(const ulonglong2*)&sKV[d * KS + tx * 8 + 4];
            ull av[4] = {splat2(a.x), splat2(a.y), splat2(a.z), splat2(a.w)};
            ull bv[4] = {b01.x, b01.y, b23.x, b23.y};
#pragma unroll
            for (int i = 0; i < 4; i++)
#pragma unroll
                for (int j = 0; j < 4; j++)
                    fma2(acc[i][j], av[i], bv[j]);
        }
        // store scaled S^T into swizzled sPT
#pragma unroll
        for (int j2 = 0; j2 < 4; j2++) {
            float2 r0 = unpack2(acc[0][j2]);
            float2 r1 = unpack2(acc[1][j2]);
            float2 r2 = unpack2(acc[2][j2]);
            float2 r3 = unpack2(acc[3][j2]);
            int j = jc * 128 + tx * 8 + j2 * 2;
            float4 v0 = make_float4(r0.x * SCALE, r1.x * SCALE, r2.x * SCALE, r3.x * SCALE);
            *(float4*)&sPT[ppos(j, ty * 4)] = v0;
            int j1 = j + 1;
            float4 v1 = make_float4(r0.y * SCALE, r1.y * SCALE, r2.y * SCALE, r3.y * SCALE);
            *(float4*)&sPT[ppos(j1, ty * 4)] = v1;
        }
        __syncthreads();
    }

    // ---- softmax (store exp; keep 1/rowsum for epilogue) ----
    {
        int i = tid & 63;
        int jg = tid >> 6;
        float mx = -1e30f;
        for (int s = 0; s < 128; s++) {
            int j = jg * 128 + s;
            mx = fmaxf(mx, sPT[ppos(j, i)]);
        }
        red[jg * 64 + i] = mx;
        __syncthreads();
        if (tid < 64)
            inv[tid] = fmaxf(fmaxf(red[tid], red[64 + tid]), fmaxf(red[128 + tid], red[192 + tid]));
        __syncthreads();
        float rmax = inv[i];
        float sum = 0.0f;
        for (int s = 0; s < 128; s++) {
            int j = jg * 128 + s;
            int idx = ppos(j, i);
            float e = __expf(sPT[idx] - rmax);
            sPT[idx] = e;
            sum += e;
        }
        red[jg * 64 + i] = sum;
        __syncthreads();
        if (tid < 64)
            inv[tid] = 1.0f / (red[tid] + red[64 + tid] + red[128 + tid] + red[192 + tid]);
        __syncthreads();
    }

    // ---- O = P V (reduction over j, 4 chunks of 128) ----
    ull oa[2][4];
#pragma unroll
    for (int i = 0; i < 2; i++)
#pragma unroll
        for (int j = 0; j < 4; j++) oa[i][j] = 0ULL;

    for (int jc = 0; jc < 4; jc++) {
        {
            int j4 = (tid & 31) * 4;
            int d0 = tid >> 5;
#pragma unroll
            for (int p = 0; p < 8; p++) {
                int d = d0 + p * 8;
                float4 v = *(const float4*)&g_qkv[voff + (size_t)d * NPOS + jc * 128 + j4];
                sKV[d * VS + j4 + 0] = v.x;
                sKV[d * VS + j4 + 1] = v.y;
                sKV[d * VS + j4 + 2] = v.z;
                sKV[d * VS + j4 + 3] = v.w;
            }
        }
        __syncthreads();
#pragma unroll 4
        for (int s = 0; s < 128; s++) {
            int j = jc * 128 + s;
            ulonglong2 ap = *(const ulonglong2*)&sPT[ppos(j, ty * 4)];
#pragma unroll
            for (int dd = 0; dd < 4; dd++) {
                ull bs = splat2(sKV[(tx * 4 + dd) * VS + s]);
                fma2(oa[0][dd], ap.x, bs);
                fma2(oa[1][dd], ap.y, bs);
            }
        }
        __syncthreads();
    }

    // ---- epilogue: normalize rows, write channel-major O ----
    float iv0 = inv[ty * 4 + 0], iv1 = inv[ty * 4 + 1];
    float iv2 = inv[ty * 4 + 2], iv3 = inv[ty * 4 + 3];
#pragma unroll
    for (int dd = 0; dd < 4; dd++) {
        float2 p0 = unpack2(oa[0][dd]);
        float2 p1 = unpack2(oa[1][dd]);
        float4 v = make_float4(p0.x * iv0, p0.y * iv1, p1.x * iv2, p1.y * iv3);
        *(float4*)&g_att[ooff + (size_t)(tx * 4 + dd) * NPOS + ty * 4] = v;
    }
}

// ---------------------------------------------------------------------------
extern "C" void kernel_launch(void* const* d_in, const int* in_sizes, int n_in,
                              void* d_out, int out_size)
{
    const float* x     = (const float*)d_in[0];
    const float* w_qkv = (const float*)d_in[1];
    const float* w_out = (const float*)d_in[2];
    const float* b_out = (const float*)d_in[3];
    float* out = (float*)d_out;

    float* qkv; cudaGetSymbolAddress((void**)&qkv, g_qkv);
    float* att; cudaGetSymbolAddress((void**)&att, g_att);

    const int smem_attn = (64 * QS + 64 * KS + 512 * 64 + 256 + 64) * 4;
    cudaFuncSetAttribute(attn_win, cudaFuncAttributeMaxDynamicSharedMemorySize, smem_attn);

    // QKV projection: [1536,256] x [256,32768] per batch
    dim3 gA(NPOS / 128, QKV_M / 128, NB);
    sgemm128<<<gA, 256>>>(w_qkv, x, qkv, nullptr, QKV_M, DIM,
                          (long long)DIM * NPOS, (long long)QKV_M * NPOS);

    // Windowed attention: 2 b * 8 h * 64 windows * 8 i-tiles = 8192 blocks
    attn_win<<<8192, 256, smem_attn>>>();

    // Output projection + bias: [256,512] x [512,32768] per batch
    dim3 gC(NPOS / 128, DIM / 128, NB);
    sgemm128<<<gC, 256>>>(w_out, att, out, b_out, DIM, HID,
                          (long long)HID * NPOS, (long long)DIM * NPOS);
}